// round 1
// baseline (speedup 1.0000x reference)
#include <cuda_runtime.h>
#include <cuda_bf16.h>
#include <math.h>
#include <stdint.h>

#define T_STEPS 1500
#define BATCH   16
#define DDIM    1024
#define HDIM    1024
#define GCOLS   4096
#define MROWS   (T_STEPS*BATCH)   // 24000
#define NCTA    128
#define HS_STRIDE 1028            // 1024 + 4 pad: conflict-free frag loads
#define YS_STRIDE 36
#define RECUR_SMEM_BYTES ((16*HS_STRIDE + 32*HS_STRIDE + 32*YS_STRIDE + 128)*4)

// ---------------- static device scratch (no runtime allocation) ----------------
__device__ float g_Wcat[(size_t)DDIM*GCOLS];      // [k][gc]  tf32-rounded
__device__ float g_UcatT[(size_t)GCOLS*HDIM];     // [gc][k]  tf32-rounded (transposed)
__device__ float g_bias[GCOLS];
__device__ float g_G[(size_t)MROWS*GCOLS];        // precomputed gate preactivations
__device__ float g_hbuf[2*BATCH*HDIM];            // double-buffered h exchange
__device__ unsigned g_bar;

// quaternion Hamilton block tables: M[p*256+a][q*256+b] = sign[p][q]*W[comp[p][q]][a][b]
__constant__ int   c_comp[16] = {0,1,2,3, 1,0,3,2, 2,3,0,1, 3,2,1,0};
__constant__ float c_sign[16] = {1.f,-1.f,-1.f,-1.f, 1.f,1.f,-1.f,1.f,
                                 1.f,1.f,1.f,-1.f,   1.f,-1.f,1.f,1.f};

__device__ __forceinline__ float tf32r(float x){
    unsigned u; asm("cvt.rna.tf32.f32 %0, %1;" : "=r"(u) : "f"(x));
    return __uint_as_float(u);
}

// ---------------- tiny setup kernels ----------------
__global__ void reset_kernel(){ g_bar = 0u; }

__global__ void expand_w_kernel(const float* __restrict__ Wf, const float* __restrict__ Wi,
                                const float* __restrict__ Wo, const float* __restrict__ Wc){
    int idx = blockIdx.x*256 + threadIdx.x;            // over 1024*4096
    int k  = idx >> 12;
    int gc = idx & 4095;
    int g = gc >> 10, hcol = gc & 1023;
    int p = k >> 8, a = k & 255;
    int q = hcol >> 8, b = hcol & 255;
    const float* W = (g==0)?Wf:(g==1)?Wi:(g==2)?Wo:Wc;
    int pq = p*4+q;
    float v = c_sign[pq] * W[c_comp[pq]*65536 + a*256 + b];
    g_Wcat[idx] = tf32r(v);
}

__global__ void expand_u_kernel(const float* __restrict__ Uf, const float* __restrict__ Ui,
                                const float* __restrict__ Uo, const float* __restrict__ Uc){
    int idx = blockIdx.x*256 + threadIdx.x;            // over 4096*1024, [gc][k]
    int gc = idx >> 10;
    int k  = idx & 1023;
    int g = gc >> 10, hcol = gc & 1023;
    int p = k >> 8, a = k & 255;
    int q = hcol >> 8, b = hcol & 255;
    const float* U = (g==0)?Uf:(g==1)?Ui:(g==2)?Uo:Uc;
    int pq = p*4+q;
    float v = c_sign[pq] * U[c_comp[pq]*65536 + a*256 + b];
    g_UcatT[idx] = tf32r(v);
}

__global__ void expand_b_kernel(const float* __restrict__ bf, const float* __restrict__ bi,
                                const float* __restrict__ bo, const float* __restrict__ bc){
    int idx = blockIdx.x*256 + threadIdx.x;
    int g = idx >> 10;
    const float* b = (g==0)?bf:(g==1)?bi:(g==2)?bo:bc;
    g_bias[idx] = b[idx & 1023];
}

// ---------------- tf32 mma helper ----------------
__device__ __forceinline__ void mma_tf32(float* d, unsigned a0, unsigned a1, unsigned a2,
                                         unsigned a3, unsigned b0, unsigned b1){
    asm volatile("mma.sync.aligned.m16n8k8.row.col.f32.tf32.tf32.f32 "
                 "{%0,%1,%2,%3}, {%4,%5,%6,%7}, {%8,%9}, {%0,%1,%2,%3};"
                 : "+f"(d[0]), "+f"(d[1]), "+f"(d[2]), "+f"(d[3])
                 : "r"(a0), "r"(a1), "r"(a2), "r"(a3), "r"(b0), "r"(b1));
}

// ---------------- precompute GEMM: g_G = x @ g_Wcat + bias ----------------
// CTA tile 128x64, BK=32, 8 warps (4x2 warp grid, warp tile 32x32), tf32 mma.
__global__ __launch_bounds__(256) void gemm_kernel(const float* __restrict__ X){
    __shared__ float As[128*36];
    __shared__ float Bs[32*72];
    int tid  = threadIdx.x;
    int wid  = tid >> 5, lane = tid & 31;
    int gi   = lane >> 2, tig = lane & 3;
    int wm   = wid & 3, wn = wid >> 2;
    int row0 = blockIdx.x*128;
    int col0 = blockIdx.y*64;

    float acc[2][4][4];
    #pragma unroll
    for (int i=0;i<2;i++)
        #pragma unroll
        for (int j=0;j<4;j++)
            #pragma unroll
            for (int l=0;l<4;l++) acc[i][j][l] = 0.f;

    for (int k0 = 0; k0 < 1024; k0 += 32) {
        #pragma unroll
        for (int p=0;p<4;p++){
            int r = p*32 + (tid>>3); int c4 = (tid&7)<<2;
            float4 v = make_float4(0.f,0.f,0.f,0.f);
            int gr = row0 + r;
            if (gr < MROWS) v = *(const float4*)(X + (size_t)gr*1024 + k0 + c4);
            v.x = tf32r(v.x); v.y = tf32r(v.y); v.z = tf32r(v.z); v.w = tf32r(v.w);
            *(float4*)(As + r*36 + c4) = v;
        }
        #pragma unroll
        for (int p=0;p<2;p++){
            int r = p*16 + (tid>>4); int c4 = (tid&15)<<2;
            *(float4*)(Bs + r*72 + c4) =
                *(const float4*)(g_Wcat + (size_t)(k0+r)*4096 + col0 + c4);
        }
        __syncthreads();
        #pragma unroll
        for (int kk=0; kk<4; ++kk){
            unsigned a[2][4], b[4][2];
            #pragma unroll
            for (int mt=0;mt<2;mt++){
                const float* pa = As + (wm*32 + mt*16 + gi)*36 + kk*8 + tig;
                a[mt][0] = __float_as_uint(pa[0]);
                a[mt][1] = __float_as_uint(pa[8*36]);
                a[mt][2] = __float_as_uint(pa[4]);
                a[mt][3] = __float_as_uint(pa[8*36+4]);
            }
            #pragma unroll
            for (int nt=0;nt<4;nt++){
                const float* pb = Bs + (kk*8+tig)*72 + wn*32 + nt*8 + gi;
                b[nt][0] = __float_as_uint(pb[0]);
                b[nt][1] = __float_as_uint(pb[4*72]);
            }
            #pragma unroll
            for (int mt=0;mt<2;mt++)
                #pragma unroll
                for (int nt=0;nt<4;nt++)
                    mma_tf32(acc[mt][nt], a[mt][0],a[mt][1],a[mt][2],a[mt][3],
                             b[nt][0], b[nt][1]);
        }
        __syncthreads();
    }
    #pragma unroll
    for (int mt=0;mt<2;mt++){
        #pragma unroll
        for (int nt=0;nt<4;nt++){
            int col = col0 + wn*32 + nt*8 + 2*tig;
            float b0 = g_bias[col], b1 = g_bias[col+1];
            int r = row0 + wm*32 + mt*16 + gi;
            if (r < MROWS)
                *(float2*)(g_G + (size_t)r*4096 + col) =
                    make_float2(acc[mt][nt][0]+b0, acc[mt][nt][1]+b1);
            if (r+8 < MROWS)
                *(float2*)(g_G + (size_t)(r+8)*4096 + col) =
                    make_float2(acc[mt][nt][2]+b0, acc[mt][nt][3]+b1);
        }
    }
}

// ---------------- persistent recurrence kernel ----------------
// 128 CTAs, each owns 8 h-columns (= 32 gate columns across f,i,o,c).
// U slice resident in smem for the whole kernel. One grid barrier per step.
__global__ __launch_bounds__(256,1) void recur_kernel(float* __restrict__ out){
    extern __shared__ float sm[];
    float* h_s = sm;                        // [16][HS_STRIDE]
    float* u_s = h_s + 16*HS_STRIDE;        // [32][HS_STRIDE]  u_s[lc][k], lc = g*8+j
    float* y_s = u_s + 32*HS_STRIDE;        // [2*16][YS_STRIDE] khalf-partials
    float* c_s = y_s + 32*YS_STRIDE;        // [16*8] cell state

    const int cta  = blockIdx.x;
    const int tid  = threadIdx.x;
    const int wid  = tid >> 5, lane = tid & 31;
    const int gi   = lane >> 2, tig = lane & 3;
    const int ntile = wid & 3;              // gate (f,i,o,c)
    const int khalf = wid >> 2;             // K half

    // one-time: load U slice (coalesced rows of g_UcatT)
    for (int lc = wid; lc < 32; lc += 8) {
        int g = lc >> 3, j = lc & 7;
        const float* src = g_UcatT + (size_t)(g*1024 + cta*8 + j)*1024;
        for (int k = lane*4; k < 1024; k += 128)
            *(float4*)(u_s + lc*HS_STRIDE + k) = *(const float4*)(src + k);
    }
    if (tid < 128) c_s[tid] = 0.f;
    __syncthreads();

    const int eb = tid >> 3, ej = tid & 7;  // epilogue element (batch, local col)
    const float* pa0 = h_s + gi*HS_STRIDE + tig;
    const float* pa1 = pa0 + 8*HS_STRIDE;
    const float* pb  = u_s + (ntile*8 + gi)*HS_STRIDE + tig;
    const int kbase  = khalf*512;

    for (int t = 0; t < T_STEPS; ++t) {
        // prefetch this step's input-side gate preactivations (overlap with mma)
        float pf=0.f, pi=0.f, po=0.f, pc=0.f;
        if (tid < 128) {
            const float* gp = g_G + (size_t)(t*16 + eb)*4096 + cta*8 + ej;
            pf = gp[0]; pi = gp[1024]; po = gp[2048]; pc = gp[3072];
        }

        float acc0[4] = {0,0,0,0}, acc1[4] = {0,0,0,0};
        if (t > 0) {
            // pull h(t-1) into smem (bypass L1: written by other SMs)
            const float* hb = g_hbuf + ((t-1)&1)*(BATCH*HDIM);
            for (int i = tid; i < BATCH*HDIM/4; i += 256) {
                int idx = i << 2; int r = idx >> 10; int c = idx & 1023;
                float4 v = __ldcg((const float4*)(hb + idx));
                *(float4*)(h_s + r*HS_STRIDE + c) = v;
            }
            __syncthreads();
            #pragma unroll 4
            for (int kt = 0; kt < 32; ++kt) {
                int kg = kbase + kt*16;
                {
                    unsigned a0=__float_as_uint(pa0[kg]),  a1=__float_as_uint(pa1[kg]);
                    unsigned a2=__float_as_uint(pa0[kg+4]),a3=__float_as_uint(pa1[kg+4]);
                    unsigned b0=__float_as_uint(pb[kg]),   b1=__float_as_uint(pb[kg+4]);
                    mma_tf32(acc0, a0,a1,a2,a3,b0,b1);
                }
                {
                    int kg2 = kg + 8;
                    unsigned a0=__float_as_uint(pa0[kg2]),  a1=__float_as_uint(pa1[kg2]);
                    unsigned a2=__float_as_uint(pa0[kg2+4]),a3=__float_as_uint(pa1[kg2+4]);
                    unsigned b0=__float_as_uint(pb[kg2]),   b1=__float_as_uint(pb[kg2+4]);
                    mma_tf32(acc1, a0,a1,a2,a3,b0,b1);
                }
            }
        }
        // dump partial sums (C-frag layout: rows gi/gi+8, cols 2*tig,2*tig+1)
        {
            float* yp = y_s + (khalf*16 + gi)*YS_STRIDE + ntile*8 + 2*tig;
            *(float2*)yp = make_float2(acc0[0]+acc1[0], acc0[1]+acc1[1]);
            *(float2*)(yp + 8*YS_STRIDE) = make_float2(acc0[2]+acc1[2], acc0[3]+acc1[3]);
        }
        __syncthreads();

        if (tid < 128) {
            const float* y0 = y_s + eb*YS_STRIDE;
            const float* y1 = y_s + (16+eb)*YS_STRIDE;
            float yf = y0[ej]    + y1[ej];
            float yi = y0[8+ej]  + y1[8+ej];
            float yo = y0[16+ej] + y1[16+ej];
            float yc = y0[24+ej] + y1[24+ej];
            float f  = 1.f/(1.f + __expf(-(pf + yf)));
            float ii = 1.f/(1.f + __expf(-(pi + yi)));
            float o  = 1.f/(1.f + __expf(-(po + yo)));
            float cn = ii * tanhf(pc + yc) * 0.8f + f * c_s[tid];
            c_s[tid] = cn;
            float h  = o * tanhf(cn);
            out[((size_t)t*16 + eb)*1024 + cta*8 + ej] = h;
            __stcg(g_hbuf + (t&1)*(BATCH*HDIM) + eb*1024 + cta*8 + ej, tf32r(h));
        }

        // grid barrier (release/acquire, double-buffered h makes 1/step sufficient)
        __syncthreads();
        if (tid == 0) {
            __threadfence();
            asm volatile("red.release.gpu.global.add.u32 [%0], 1;" :: "l"(&g_bar) : "memory");
            unsigned target = (unsigned)(t+1) * NCTA;
            unsigned v;
            for (;;) {
                asm volatile("ld.acquire.gpu.global.u32 %0, [%1];"
                             : "=r"(v) : "l"(&g_bar) : "memory");
                if (v >= target) break;
                __nanosleep(20);
            }
        }
        __syncthreads();
    }
}

// ---------------- launch ----------------
extern "C" void kernel_launch(void* const* d_in, const int* in_sizes, int n_in,
                              void* d_out, int out_size) {
    const float* x  = (const float*)d_in[0];
    const float* Wf = (const float*)d_in[1];
    const float* Wi = (const float*)d_in[2];
    const float* Wo = (const float*)d_in[3];
    const float* Wc = (const float*)d_in[4];
    const float* bf = (const float*)d_in[5];
    const float* bi = (const float*)d_in[6];
    const float* bo = (const float*)d_in[7];
    const float* bc = (const float*)d_in[8];
    const float* Uf = (const float*)d_in[9];
    const float* Ui = (const float*)d_in[10];
    const float* Uo = (const float*)d_in[11];
    const float* Uc = (const float*)d_in[12];
    float* out = (float*)d_out;

    cudaFuncSetAttribute(recur_kernel, cudaFuncAttributeMaxDynamicSharedMemorySize,
                         RECUR_SMEM_BYTES);

    reset_kernel<<<1,1>>>();
    expand_w_kernel<<<(DDIM*GCOLS)/256, 256>>>(Wf, Wi, Wo, Wc);
    expand_u_kernel<<<(GCOLS*HDIM)/256, 256>>>(Uf, Ui, Uo, Uc);
    expand_b_kernel<<<GCOLS/256, 256>>>(bf, bi, bo, bc);
    gemm_kernel<<<dim3((MROWS+127)/128, GCOLS/64), 256>>>(x);
    recur_kernel<<<NCTA, 256, RECUR_SMEM_BYTES>>>(out);
}

// round 2
// speedup vs baseline: 1.5568x; 1.5568x over previous
#include <cuda_runtime.h>
#include <cuda_fp16.h>
#include <math.h>
#include <stdint.h>

#define T_STEPS 1500
#define BATCH   16
#define DDIM    1024
#define HDIM    1024
#define GCOLS   4096
#define MROWS   (T_STEPS*BATCH)   // 24000
#define NCTA    128
#define HS_HALF 1032              // halves per h_s row (1024 + 8 pad -> word stride 516 = 4 mod 32)
#define US_HALF 1032
#define YROW    36
#define RECUR_SMEM_BYTES (32*US_HALF*2 + 16*HS_HALF*2 + 128*YROW*4 + 256)

// ---------------- static device scratch ----------------
__device__ float  g_Wcat[(size_t)DDIM*GCOLS];      // [k][gc] tf32-rounded (input GEMM)
__device__ __half g_UcatT[(size_t)GCOLS*HDIM];     // [gc][k] fp16 (recurrent weights)
__device__ float  g_bias[GCOLS];
__device__ float  g_G[(size_t)MROWS*GCOLS];        // gate preactivations
__device__ __half g_hbuf[2*BATCH*HDIM];            // double-buffered h exchange (fp16)
__device__ unsigned g_bar;

// quaternion Hamilton block tables
__constant__ int   c_comp[16] = {0,1,2,3, 1,0,3,2, 2,3,0,1, 3,2,1,0};
__constant__ float c_sign[16] = {1.f,-1.f,-1.f,-1.f, 1.f,1.f,-1.f,1.f,
                                 1.f,1.f,1.f,-1.f,   1.f,-1.f,1.f,1.f};

__device__ __forceinline__ float tf32r(float x){
    unsigned u; asm("cvt.rna.tf32.f32 %0, %1;" : "=r"(u) : "f"(x));
    return __uint_as_float(u);
}

// ---------------- setup kernels ----------------
__global__ void reset_kernel(){ g_bar = 0u; }

__global__ void expand_w_kernel(const float* __restrict__ Wf, const float* __restrict__ Wi,
                                const float* __restrict__ Wo, const float* __restrict__ Wc){
    int idx = blockIdx.x*256 + threadIdx.x;            // over 1024*4096
    int k  = idx >> 12;
    int gc = idx & 4095;
    int g = gc >> 10, hcol = gc & 1023;
    int p = k >> 8, a = k & 255;
    int q = hcol >> 8, b = hcol & 255;
    const float* W = (g==0)?Wf:(g==1)?Wi:(g==2)?Wo:Wc;
    int pq = p*4+q;
    float v = c_sign[pq] * W[c_comp[pq]*65536 + a*256 + b];
    g_Wcat[idx] = tf32r(v);
}

__global__ void expand_u_kernel(const float* __restrict__ Uf, const float* __restrict__ Ui,
                                const float* __restrict__ Uo, const float* __restrict__ Uc){
    int idx = blockIdx.x*256 + threadIdx.x;            // over 4096*1024, [gc][k]
    int gc = idx >> 10;
    int k  = idx & 1023;
    int g = gc >> 10, hcol = gc & 1023;
    int p = k >> 8, a = k & 255;
    int q = hcol >> 8, b = hcol & 255;
    const float* U = (g==0)?Uf:(g==1)?Ui:(g==2)?Uo:Uc;
    int pq = p*4+q;
    float v = c_sign[pq] * U[c_comp[pq]*65536 + a*256 + b];
    g_UcatT[idx] = __float2half_rn(v);
}

__global__ void expand_b_kernel(const float* __restrict__ bf, const float* __restrict__ bi,
                                const float* __restrict__ bo, const float* __restrict__ bc){
    int idx = blockIdx.x*256 + threadIdx.x;
    int g = idx >> 10;
    const float* b = (g==0)?bf:(g==1)?bi:(g==2)?bo:bc;
    g_bias[idx] = b[idx & 1023];
}

// ---------------- mma helpers ----------------
__device__ __forceinline__ void mma_tf32(float* d, unsigned a0, unsigned a1, unsigned a2,
                                         unsigned a3, unsigned b0, unsigned b1){
    asm volatile("mma.sync.aligned.m16n8k8.row.col.f32.tf32.tf32.f32 "
                 "{%0,%1,%2,%3}, {%4,%5,%6,%7}, {%8,%9}, {%0,%1,%2,%3};"
                 : "+f"(d[0]), "+f"(d[1]), "+f"(d[2]), "+f"(d[3])
                 : "r"(a0), "r"(a1), "r"(a2), "r"(a3), "r"(b0), "r"(b1));
}

__device__ __forceinline__ void mma_fp16(float* d, unsigned a0, unsigned a1, unsigned a2,
                                         unsigned a3, unsigned b0, unsigned b1){
    asm volatile("mma.sync.aligned.m16n8k16.row.col.f32.f16.f16.f32 "
                 "{%0,%1,%2,%3}, {%4,%5,%6,%7}, {%8,%9}, {%0,%1,%2,%3};"
                 : "+f"(d[0]), "+f"(d[1]), "+f"(d[2]), "+f"(d[3])
                 : "r"(a0), "r"(a1), "r"(a2), "r"(a3), "r"(b0), "r"(b1));
}

// ---------------- precompute GEMM: g_G = x @ g_Wcat + bias (tf32) ----------------
__global__ __launch_bounds__(256) void gemm_kernel(const float* __restrict__ X){
    __shared__ float As[128*36];
    __shared__ float Bs[32*72];
    int tid  = threadIdx.x;
    int wid  = tid >> 5, lane = tid & 31;
    int gi   = lane >> 2, tig = lane & 3;
    int wm   = wid & 3, wn = wid >> 2;
    int row0 = blockIdx.x*128;
    int col0 = blockIdx.y*64;

    float acc[2][4][4];
    #pragma unroll
    for (int i=0;i<2;i++)
        #pragma unroll
        for (int j=0;j<4;j++)
            #pragma unroll
            for (int l=0;l<4;l++) acc[i][j][l] = 0.f;

    for (int k0 = 0; k0 < 1024; k0 += 32) {
        #pragma unroll
        for (int p=0;p<4;p++){
            int r = p*32 + (tid>>3); int c4 = (tid&7)<<2;
            float4 v = make_float4(0.f,0.f,0.f,0.f);
            int gr = row0 + r;
            if (gr < MROWS) v = *(const float4*)(X + (size_t)gr*1024 + k0 + c4);
            v.x = tf32r(v.x); v.y = tf32r(v.y); v.z = tf32r(v.z); v.w = tf32r(v.w);
            *(float4*)(As + r*36 + c4) = v;
        }
        #pragma unroll
        for (int p=0;p<2;p++){
            int r = p*16 + (tid>>4); int c4 = (tid&15)<<2;
            *(float4*)(Bs + r*72 + c4) =
                *(const float4*)(g_Wcat + (size_t)(k0+r)*4096 + col0 + c4);
        }
        __syncthreads();
        #pragma unroll
        for (int kk=0; kk<4; ++kk){
            unsigned a[2][4], b[4][2];
            #pragma unroll
            for (int mt=0;mt<2;mt++){
                const float* pa = As + (wm*32 + mt*16 + gi)*36 + kk*8 + tig;
                a[mt][0] = __float_as_uint(pa[0]);
                a[mt][1] = __float_as_uint(pa[8*36]);
                a[mt][2] = __float_as_uint(pa[4]);
                a[mt][3] = __float_as_uint(pa[8*36+4]);
            }
            #pragma unroll
            for (int nt=0;nt<4;nt++){
                const float* pb = Bs + (kk*8+tig)*72 + wn*32 + nt*8 + gi;
                b[nt][0] = __float_as_uint(pb[0]);
                b[nt][1] = __float_as_uint(pb[4*72]);
            }
            #pragma unroll
            for (int mt=0;mt<2;mt++)
                #pragma unroll
                for (int nt=0;nt<4;nt++)
                    mma_tf32(acc[mt][nt], a[mt][0],a[mt][1],a[mt][2],a[mt][3],
                             b[nt][0], b[nt][1]);
        }
        __syncthreads();
    }
    #pragma unroll
    for (int mt=0;mt<2;mt++){
        #pragma unroll
        for (int nt=0;nt<4;nt++){
            int col = col0 + wn*32 + nt*8 + 2*tig;
            float b0 = g_bias[col], b1 = g_bias[col+1];
            int r = row0 + wm*32 + mt*16 + gi;
            if (r < MROWS)
                *(float2*)(g_G + (size_t)r*4096 + col) =
                    make_float2(acc[mt][nt][0]+b0, acc[mt][nt][1]+b1);
            if (r+8 < MROWS)
                *(float2*)(g_G + (size_t)(r+8)*4096 + col) =
                    make_float2(acc[mt][nt][2]+b0, acc[mt][nt][3]+b1);
        }
    }
}

// ---------------- persistent recurrence kernel (fp16 feed) ----------------
// 128 CTAs x 256 threads. CTA owns 8 h-cols (32 gate cols). Warp w covers
// k range [w*128, w*128+128) over ALL 32 gate cols (max A-fragment reuse).
__global__ __launch_bounds__(256,1) void recur_kernel(float* __restrict__ out){
    extern __shared__ char smraw[];
    __half* u_s = (__half*)smraw;                   // [32][US_HALF]
    __half* h_s = u_s + 32*US_HALF;                 // [16][HS_HALF]
    float*  y_s = (float*)(h_s + 16*HS_HALF);       // [8*16][YROW]

    const int cta  = blockIdx.x;
    const int tid  = threadIdx.x;
    const int wid  = tid >> 5, lane = tid & 31;
    const int gi   = lane >> 2, tig = lane & 3;

    // one-time: load fp16 U slice
    for (int lc = wid; lc < 32; lc += 8) {
        int g = lc >> 3, j = lc & 7;
        const __half* src = g_UcatT + (size_t)(g*1024 + cta*8 + j)*1024;
        for (int k = lane*8; k < 1024; k += 256)
            *(float4*)(u_s + lc*US_HALF + k) = *(const float4*)(src + k);
    }
    __syncthreads();

    const int eb = tid >> 3, ej = tid & 7;          // epilogue element
    float c_reg = 0.f;
    float pf=0.f, pi=0.f, po=0.f, pc=0.f;
    if (tid < 128) {
        const float* gp = g_G + (size_t)eb*4096 + cta*8 + ej;
        pf = gp[0]; pi = gp[1024]; po = gp[2048]; pc = gp[3072];
    }

    const int kw = wid*128;                          // this warp's k base
    const unsigned* aw0 = (const unsigned*)h_s + gi*(HS_HALF/2) + tig + kw/2;
    const unsigned* bw0 = (const unsigned*)u_s + gi*(US_HALF/2) + tig + kw/2;

    for (int t = 0; t < T_STEPS; ++t) {
        float acc[4][4];
        #pragma unroll
        for (int n=0;n<4;n++){ acc[n][0]=0.f; acc[n][1]=0.f; acc[n][2]=0.f; acc[n][3]=0.f; }

        if (t > 0) {
            // pull h(t-1) (fp16) into smem, L2 path
            const __half* hb = g_hbuf + ((t-1)&1)*(BATCH*HDIM);
            #pragma unroll
            for (int i = 0; i < 8; ++i) {
                int idx8 = (i*256 + tid) * 8;        // half index
                int r = idx8 >> 10, cc = idx8 & 1023;
                float4 v = __ldcg((const float4*)(hb + idx8));
                *(float4*)(h_s + r*HS_HALF + cc) = v;
            }
            __syncthreads();
            #pragma unroll
            for (int kc = 0; kc < 8; ++kc) {
                int o = kc*8;                        // 16 halves per chunk = 8 words
                unsigned a0 = aw0[o];
                unsigned a1 = aw0[o + 8*(HS_HALF/2)];
                unsigned a2 = aw0[o + 4];
                unsigned a3 = aw0[o + 4 + 8*(HS_HALF/2)];
                #pragma unroll
                for (int nt = 0; nt < 4; ++nt) {
                    unsigned b0 = bw0[o + nt*8*(US_HALF/2)];
                    unsigned b1 = bw0[o + 4 + nt*8*(US_HALF/2)];
                    mma_fp16(acc[nt], a0,a1,a2,a3,b0,b1);
                }
            }
        }
        // dump partial sums: warp wid, rows gi / gi+8, cols nt*8 + 2*tig
        {
            float* yp0 = y_s + (wid*16 + gi)*YROW + 2*tig;
            float* yp1 = y_s + (wid*16 + gi + 8)*YROW + 2*tig;
            #pragma unroll
            for (int nt = 0; nt < 4; ++nt) {
                *(float2*)(yp0 + nt*8) = make_float2(acc[nt][0], acc[nt][1]);
                *(float2*)(yp1 + nt*8) = make_float2(acc[nt][2], acc[nt][3]);
            }
        }
        __syncthreads();

        if (tid < 128) {
            float yf=0.f, yi=0.f, yo=0.f, yc=0.f;
            #pragma unroll
            for (int w = 0; w < 8; ++w) {
                const float* yr = y_s + (w*16 + eb)*YROW + ej;
                yf += yr[0]; yi += yr[8]; yo += yr[16]; yc += yr[24];
            }
            float f  = 1.f/(1.f + __expf(-(pf + yf)));
            float ii = 1.f/(1.f + __expf(-(pi + yi)));
            float o  = 1.f/(1.f + __expf(-(po + yo)));
            float cn = fmaf(f, c_reg, ii * tanhf(pc + yc) * 0.8f);
            c_reg = cn;
            float h  = o * tanhf(cn);
            out[((size_t)t*16 + eb)*1024 + cta*8 + ej] = h;
            unsigned short hh = __half_as_ushort(__float2half_rn(h));
            asm volatile("st.global.cg.u16 [%0], %1;"
                         :: "l"(g_hbuf + (t&1)*(BATCH*HDIM) + eb*1024 + cta*8 + ej),
                            "h"(hh) : "memory");
            // prefetch next step's G during barrier wait
            if (t + 1 < T_STEPS) {
                const float* gp = g_G + (size_t)((t+1)*16 + eb)*4096 + cta*8 + ej;
                pf = gp[0]; pi = gp[1024]; po = gp[2048]; pc = gp[3072];
            }
        }

        // grid barrier (release/acquire)
        __syncthreads();
        if (tid == 0) {
            asm volatile("red.release.gpu.global.add.u32 [%0], 1;" :: "l"(&g_bar) : "memory");
            unsigned target = (unsigned)(t+1) * NCTA;
            unsigned v;
            for (;;) {
                asm volatile("ld.acquire.gpu.global.u32 %0, [%1];"
                             : "=r"(v) : "l"(&g_bar) : "memory");
                if (v >= target) break;
                __nanosleep(20);
            }
        }
        __syncthreads();
    }
}

// ---------------- launch ----------------
extern "C" void kernel_launch(void* const* d_in, const int* in_sizes, int n_in,
                              void* d_out, int out_size) {
    const float* x  = (const float*)d_in[0];
    const float* Wf = (const float*)d_in[1];
    const float* Wi = (const float*)d_in[2];
    const float* Wo = (const float*)d_in[3];
    const float* Wc = (const float*)d_in[4];
    const float* bf = (const float*)d_in[5];
    const float* bi = (const float*)d_in[6];
    const float* bo = (const float*)d_in[7];
    const float* bc = (const float*)d_in[8];
    const float* Uf = (const float*)d_in[9];
    const float* Ui = (const float*)d_in[10];
    const float* Uo = (const float*)d_in[11];
    const float* Uc = (const float*)d_in[12];
    float* out = (float*)d_out;

    cudaFuncSetAttribute(recur_kernel, cudaFuncAttributeMaxDynamicSharedMemorySize,
                         RECUR_SMEM_BYTES);

    reset_kernel<<<1,1>>>();
    expand_w_kernel<<<(DDIM*GCOLS)/256, 256>>>(Wf, Wi, Wo, Wc);
    expand_u_kernel<<<(GCOLS*HDIM)/256, 256>>>(Uf, Ui, Uo, Uc);
    expand_b_kernel<<<GCOLS/256, 256>>>(bf, bi, bo, bc);
    gemm_kernel<<<dim3((MROWS+127)/128, GCOLS/64), 256>>>(x);
    recur_kernel<<<NCTA, 256, RECUR_SMEM_BYTES>>>(out);
}

// round 3
// speedup vs baseline: 1.5929x; 1.0232x over previous
#include <cuda_runtime.h>
#include <cuda_fp16.h>
#include <math.h>
#include <stdint.h>

#define T_STEPS 1500
#define BATCH   16
#define DDIM    1024
#define HDIM    1024
#define GCOLS   4096
#define MROWS   (T_STEPS*BATCH)   // 24000
#define NCTA    128
#define HS_HALF 1032              // h_s row stride in halves (word stride 516: conflict-free)
#define US_HALF 1032
#define YROW    36
#define RECUR_SMEM_BYTES (32*US_HALF*2 + 16*HS_HALF*2 + 128*YROW*4 + 256)

// ---------------- static device scratch ----------------
__device__ __half g_WcatT[(size_t)GCOLS*DDIM];     // [gc][k] fp16 (input weights)
__device__ __half g_UcatT[(size_t)GCOLS*HDIM];     // [gc][k] fp16 (recurrent weights)
__device__ __half g_Xh[(size_t)MROWS*DDIM];        // fp16 copy of x
__device__ float  g_bias[GCOLS];
__device__ float  g_G[(size_t)MROWS*GCOLS];        // gate preactivations
__device__ __half g_hbuf[2*BATCH*HDIM];            // double-buffered h exchange (fp16)
__device__ unsigned g_chunk[8*32];                 // 8 chunk counters, 128B apart

// quaternion Hamilton block tables
__constant__ int   c_comp[16] = {0,1,2,3, 1,0,3,2, 2,3,0,1, 3,2,1,0};
__constant__ float c_sign[16] = {1.f,-1.f,-1.f,-1.f, 1.f,1.f,-1.f,1.f,
                                 1.f,1.f,1.f,-1.f,   1.f,-1.f,1.f,1.f};

// ---------------- setup kernels ----------------
__global__ void reset_kernel(){ g_chunk[threadIdx.x] = 0u; }

__global__ void expand_w_kernel(const float* __restrict__ Wf, const float* __restrict__ Wi,
                                const float* __restrict__ Wo, const float* __restrict__ Wc){
    int idx = blockIdx.x*256 + threadIdx.x;            // over 4096*1024, [gc][k]
    int gc = idx >> 10;
    int k  = idx & 1023;
    int g = gc >> 10, hcol = gc & 1023;
    int p = k >> 8, a = k & 255;
    int q = hcol >> 8, b = hcol & 255;
    const float* W = (g==0)?Wf:(g==1)?Wi:(g==2)?Wo:Wc;
    int pq = p*4+q;
    float v = c_sign[pq] * W[c_comp[pq]*65536 + a*256 + b];
    g_WcatT[idx] = __float2half_rn(v);
}

__global__ void expand_u_kernel(const float* __restrict__ Uf, const float* __restrict__ Ui,
                                const float* __restrict__ Uo, const float* __restrict__ Uc){
    int idx = blockIdx.x*256 + threadIdx.x;            // over 4096*1024, [gc][k]
    int gc = idx >> 10;
    int k  = idx & 1023;
    int g = gc >> 10, hcol = gc & 1023;
    int p = k >> 8, a = k & 255;
    int q = hcol >> 8, b = hcol & 255;
    const float* U = (g==0)?Uf:(g==1)?Ui:(g==2)?Uo:Uc;
    int pq = p*4+q;
    float v = c_sign[pq] * U[c_comp[pq]*65536 + a*256 + b];
    g_UcatT[idx] = __float2half_rn(v);
}

__global__ void expand_b_kernel(const float* __restrict__ bf, const float* __restrict__ bi,
                                const float* __restrict__ bo, const float* __restrict__ bc){
    int idx = blockIdx.x*256 + threadIdx.x;
    int g = idx >> 10;
    const float* b = (g==0)?bf:(g==1)?bi:(g==2)?bo:bc;
    g_bias[idx] = b[idx & 1023];
}

__global__ void convert_x_kernel(const float* __restrict__ X){
    int i = blockIdx.x*256 + threadIdx.x;              // over MROWS*1024/4
    float4 v = *(const float4*)(X + (size_t)i*4);
    __half2 h0 = __floats2half2_rn(v.x, v.y);
    __half2 h1 = __floats2half2_rn(v.z, v.w);
    *(__half2*)(g_Xh + (size_t)i*4)     = h0;
    *(__half2*)(g_Xh + (size_t)i*4 + 2) = h1;
}

// ---------------- fp16 mma helper ----------------
__device__ __forceinline__ void mma_fp16(float* d, unsigned a0, unsigned a1, unsigned a2,
                                         unsigned a3, unsigned b0, unsigned b1){
    asm volatile("mma.sync.aligned.m16n8k16.row.col.f32.f16.f16.f32 "
                 "{%0,%1,%2,%3}, {%4,%5,%6,%7}, {%8,%9}, {%0,%1,%2,%3};"
                 : "+f"(d[0]), "+f"(d[1]), "+f"(d[2]), "+f"(d[3])
                 : "r"(a0), "r"(a1), "r"(a2), "r"(a3), "r"(b0), "r"(b1));
}

__device__ __forceinline__ float fast_sigmoid(float x){
    return __fdividef(1.f, 1.f + __expf(-x));
}
__device__ __forceinline__ float fast_tanh(float x){
    float e = __expf(2.f * x);
    return 1.f - __fdividef(2.f, e + 1.f);
}

// ---------------- precompute GEMM: g_G = Xh @ WcatT^T + bias (fp16) ----------------
// CTA tile 128x64, BK=64, 8 warps (4x2), warp tile 32x32.
#define A_ST 72   // halves per As row (64 + 8) -> word stride 36: conflict-free
__global__ __launch_bounds__(256) void gemm_kernel(){
    __shared__ __half As[128*A_ST];
    __shared__ __half Bs[64*A_ST];
    int tid  = threadIdx.x;
    int wid  = tid >> 5, lane = tid & 31;
    int gi   = lane >> 2, tig = lane & 3;
    int wm   = wid & 3, wn = wid >> 2;
    int row0 = blockIdx.x*128;
    int col0 = blockIdx.y*64;

    float acc[2][4][4];
    #pragma unroll
    for (int i=0;i<2;i++)
        #pragma unroll
        for (int j=0;j<4;j++)
            #pragma unroll
            for (int l=0;l<4;l++) acc[i][j][l] = 0.f;

    for (int k0 = 0; k0 < 1024; k0 += 64) {
        // As: 128 rows x 64 halves  (1024 float4, 4 per thread)
        #pragma unroll
        for (int p=0;p<4;p++){
            int f = p*256 + tid;
            int r = f >> 3, c8 = (f & 7) * 8;
            float4 v = make_float4(0.f,0.f,0.f,0.f);
            int gr = row0 + r;
            if (gr < MROWS) v = *(const float4*)(g_Xh + (size_t)gr*1024 + k0 + c8);
            *(float4*)(As + r*A_ST + c8) = v;
        }
        // Bs: 64 rows x 64 halves (512 float4, 2 per thread)
        #pragma unroll
        for (int p=0;p<2;p++){
            int f = p*256 + tid;
            int r = f >> 3, c8 = (f & 7) * 8;
            *(float4*)(Bs + r*A_ST + c8) =
                *(const float4*)(g_WcatT + (size_t)(col0 + r)*1024 + k0 + c8);
        }
        __syncthreads();
        const unsigned* Aw = (const unsigned*)As;
        const unsigned* Bw = (const unsigned*)Bs;
        #pragma unroll
        for (int kk = 0; kk < 4; ++kk){
            int ko = kk*8 + tig;                       // word offset within row
            unsigned a[2][4], b[4][2];
            #pragma unroll
            for (int mt=0;mt<2;mt++){
                int r = wm*32 + mt*16 + gi;
                a[mt][0] = Aw[r*36 + ko];
                a[mt][1] = Aw[(r+8)*36 + ko];
                a[mt][2] = Aw[r*36 + ko + 4];
                a[mt][3] = Aw[(r+8)*36 + ko + 4];
            }
            #pragma unroll
            for (int nt=0;nt<4;nt++){
                int n = wn*32 + nt*8 + gi;
                b[nt][0] = Bw[n*36 + ko];
                b[nt][1] = Bw[n*36 + ko + 4];
            }
            #pragma unroll
            for (int mt=0;mt<2;mt++)
                #pragma unroll
                for (int nt=0;nt<4;nt++)
                    mma_fp16(acc[mt][nt], a[mt][0],a[mt][1],a[mt][2],a[mt][3],
                             b[nt][0], b[nt][1]);
        }
        __syncthreads();
    }
    #pragma unroll
    for (int mt=0;mt<2;mt++){
        #pragma unroll
        for (int nt=0;nt<4;nt++){
            int col = col0 + wn*32 + nt*8 + 2*tig;
            float b0 = g_bias[col], b1 = g_bias[col+1];
            int r = row0 + wm*32 + mt*16 + gi;
            if (r < MROWS)
                *(float2*)(g_G + (size_t)r*4096 + col) =
                    make_float2(acc[mt][nt][0]+b0, acc[mt][nt][1]+b1);
            if (r+8 < MROWS)
                *(float2*)(g_G + (size_t)(r+8)*4096 + col) =
                    make_float2(acc[mt][nt][2]+b0, acc[mt][nt][3]+b1);
        }
    }
}

// ---------------- persistent recurrence kernel, chunked producer/consumer sync ----
// 128 CTAs x 256 threads. CTA owns 8 h-cols (32 gate cols). Warp w consumes
// k slice [128w,128w+128) = h-cols produced by CTAs 16w..16w+15 -> per-chunk
// counters replace the full grid barrier.
__global__ __launch_bounds__(256,1) void recur_kernel(float* __restrict__ out){
    extern __shared__ char smraw[];
    __half* u_s = (__half*)smraw;                   // [32][US_HALF]
    __half* h_s = u_s + 32*US_HALF;                 // [16][HS_HALF]
    float*  y_s = (float*)(h_s + 16*HS_HALF);       // [8*16][YROW]

    const int cta  = blockIdx.x;
    const int tid  = threadIdx.x;
    const int wid  = tid >> 5, lane = tid & 31;
    const int gi   = lane >> 2, tig = lane & 3;

    // one-time: load fp16 U slice (32 gate cols x 1024 k)
    for (int lc = wid; lc < 32; lc += 8) {
        int g = lc >> 3, j = lc & 7;
        const __half* src = g_UcatT + (size_t)(g*1024 + cta*8 + j)*1024;
        for (int k = lane*8; k < 1024; k += 256)
            *(float4*)(u_s + lc*US_HALF + k) = *(const float4*)(src + k);
    }
    __syncthreads();

    const int eb = tid >> 3, ej = tid & 7;          // epilogue element
    float c_reg = 0.f;
    float pf=0.f, pi=0.f, po=0.f, pc=0.f;
    if (tid < 128) {
        const float* gp = g_G + (size_t)eb*4096 + cta*8 + ej;
        pf = gp[0]; pi = gp[1024]; po = gp[2048]; pc = gp[3072];
    }

    const int kw = wid*128;                          // this warp's k base (halves)
    const unsigned* aw0 = (const unsigned*)h_s + gi*(HS_HALF/2) + tig + kw/2;
    const unsigned* bw0 = (const unsigned*)u_s + gi*(US_HALF/2) + tig + kw/2;
    unsigned* my_ctr   = g_chunk + wid*32;           // counter this warp consumes
    unsigned* prod_ctr = g_chunk + (cta>>4)*32;      // counter this CTA produces

    for (int t = 0; t < T_STEPS; ++t) {
        float acc[4][4];
        #pragma unroll
        for (int n=0;n<4;n++){ acc[n][0]=0.f; acc[n][1]=0.f; acc[n][2]=0.f; acc[n][3]=0.f; }

        if (t > 0) {
            // wait only for this chunk's 16 producers
            if (lane == 0) {
                unsigned target = (unsigned)t * 16u;
                unsigned v;
                for (;;) {
                    asm volatile("ld.acquire.gpu.global.u32 %0, [%1];"
                                 : "=r"(v) : "l"(my_ctr) : "memory");
                    if (v >= target) break;
                    __nanosleep(24);
                }
            }
            __syncwarp();
            // load this warp's 16x128-half chunk of h(t-1)
            const __half* hb = g_hbuf + ((t-1)&1)*(BATCH*HDIM) + kw;
            #pragma unroll
            for (int i = 0; i < 8; ++i) {
                int f = i*32 + lane;
                int r = f >> 4, c8 = (f & 15) * 8;
                float4 v = __ldcg((const float4*)(hb + r*1024 + c8));
                *(float4*)(h_s + r*HS_HALF + kw + c8) = v;
            }
            __syncwarp();
            #pragma unroll
            for (int kc = 0; kc < 8; ++kc) {
                int o = kc*8;                        // 16 halves per chunk = 8 words
                unsigned a0 = aw0[o];
                unsigned a1 = aw0[o + 8*(HS_HALF/2)];
                unsigned a2 = aw0[o + 4];
                unsigned a3 = aw0[o + 4 + 8*(HS_HALF/2)];
                #pragma unroll
                for (int nt = 0; nt < 4; ++nt) {
                    unsigned b0 = bw0[o + nt*8*(US_HALF/2)];
                    unsigned b1 = bw0[o + 4 + nt*8*(US_HALF/2)];
                    mma_fp16(acc[nt], a0,a1,a2,a3,b0,b1);
                }
            }
        }
        // dump partial sums: warp wid, rows gi / gi+8, cols nt*8 + 2*tig
        {
            float* yp0 = y_s + (wid*16 + gi)*YROW + 2*tig;
            float* yp1 = y_s + (wid*16 + gi + 8)*YROW + 2*tig;
            #pragma unroll
            for (int nt = 0; nt < 4; ++nt) {
                *(float2*)(yp0 + nt*8) = make_float2(acc[nt][0], acc[nt][1]);
                *(float2*)(yp1 + nt*8) = make_float2(acc[nt][2], acc[nt][3]);
            }
        }
        __syncthreads();

        if (tid < 128) {
            float yf=0.f, yi=0.f, yo=0.f, yc=0.f;
            #pragma unroll
            for (int w = 0; w < 8; ++w) {
                const float* yr = y_s + (w*16 + eb)*YROW + ej;
                yf += yr[0]; yi += yr[8]; yo += yr[16]; yc += yr[24];
            }
            float f  = fast_sigmoid(pf + yf);
            float ii = fast_sigmoid(pi + yi);
            float o  = fast_sigmoid(po + yo);
            float cn = fmaf(f, c_reg, ii * fast_tanh(pc + yc) * 0.8f);
            c_reg = cn;
            float h  = o * fast_tanh(cn);
            out[((size_t)t*16 + eb)*1024 + cta*8 + ej] = h;
            unsigned short hh = __half_as_ushort(__float2half_rn(h));
            asm volatile("st.global.cg.u16 [%0], %1;"
                         :: "l"(g_hbuf + (t&1)*(BATCH*HDIM) + eb*1024 + cta*8 + ej),
                            "h"(hh) : "memory");
            asm volatile("membar.gl;" ::: "memory");
            // prefetch next step's G (retires under next step's wait/mma)
            if (t + 1 < T_STEPS) {
                const float* gp = g_G + (size_t)((t+1)*16 + eb)*4096 + cta*8 + ej;
                pf = gp[0]; pi = gp[1024]; po = gp[2048]; pc = gp[3072];
            }
        }

        __syncthreads();
        if (tid == 0)
            asm volatile("red.release.gpu.global.add.u32 [%0], 1;"
                         :: "l"(prod_ctr) : "memory");
    }
}

// ---------------- launch ----------------
extern "C" void kernel_launch(void* const* d_in, const int* in_sizes, int n_in,
                              void* d_out, int out_size) {
    const float* x  = (const float*)d_in[0];
    const float* Wf = (const float*)d_in[1];
    const float* Wi = (const float*)d_in[2];
    const float* Wo = (const float*)d_in[3];
    const float* Wc = (const float*)d_in[4];
    const float* bf = (const float*)d_in[5];
    const float* bi = (const float*)d_in[6];
    const float* bo = (const float*)d_in[7];
    const float* bc = (const float*)d_in[8];
    const float* Uf = (const float*)d_in[9];
    const float* Ui = (const float*)d_in[10];
    const float* Uo = (const float*)d_in[11];
    const float* Uc = (const float*)d_in[12];
    float* out = (float*)d_out;

    cudaFuncSetAttribute(recur_kernel, cudaFuncAttributeMaxDynamicSharedMemorySize,
                         RECUR_SMEM_BYTES);

    reset_kernel<<<1,256>>>();
    expand_w_kernel<<<(GCOLS*DDIM)/256, 256>>>(Wf, Wi, Wo, Wc);
    expand_u_kernel<<<(GCOLS*HDIM)/256, 256>>>(Uf, Ui, Uo, Uc);
    expand_b_kernel<<<GCOLS/256, 256>>>(bf, bi, bo, bc);
    convert_x_kernel<<<(MROWS*DDIM/4)/256, 256>>>(x);
    gemm_kernel<<<dim3((MROWS+127)/128, GCOLS/64), 256>>>();
    recur_kernel<<<NCTA, 256, RECUR_SMEM_BYTES>>>(out);
}